// round 2
// baseline (speedup 1.0000x reference)
#include <cuda_runtime.h>
#include <cstdint>
#include <cstddef>

// Problem constants
#define NUM_K 512
#define DIM   64
#define T_LEN 8192
#define B_LEN 32

// Tiling
#define MT   256      // vectors per CTA
#define NTH  256      // threads per CTA
#define VT   4        // vectors per thread
#define KPP  8        // code-PAIRS per inner pass (16 codes)
#define NTY  4        // code-group split (tid>>6)
#define NPASS 8       // (256 pairs / NTY) / KPP

// emb pair row pitch in ull (64 + 1 pad -> kills gather bank conflicts)
#define EP_ULL 65

// Output layout: [quantized (B*D*T)] [loss (1)] [indices as float (B*T)]
#define LOSS_OFF ((size_t)B_LEN * DIM * T_LEN)
#define IDX_OFF  (LOSS_OFF + 1)

#define NBLOCKS ((B_LEN * T_LEN) / MT)   // 1024

typedef unsigned long long ull;

__device__ double g_partial[NBLOCKS];
__device__ float  g_ee[NUM_K];

__device__ __forceinline__ void fma2(ull &acc, ull a, ull b) {
    asm("fma.rn.f32x2 %0, %1, %2, %0;" : "+l"(acc) : "l"(a), "l"(b));
}
__device__ __forceinline__ float2 unpack2(ull v) {
    float2 r;
    asm("mov.b64 {%0, %1}, %2;" : "=f"(r.x), "=f"(r.y) : "l"(v));
    return r;
}
__device__ __forceinline__ ull dup2(float x) {
    ull r;
    asm("mov.b64 %0, {%1, %1};" : "=l"(r) : "f"(x));
    return r;
}

// ---------------------------------------------------------------------------
// Pass 0: per-code squared norms (sequential order; order provably irrelevant)
// ---------------------------------------------------------------------------
__global__ void vq_prep(const float* __restrict__ emb) {
    int k = threadIdx.x;
    if (k < NUM_K) {
        const float* r = emb + k * DIM;
        float s = 0.f;
#pragma unroll
        for (int d = 0; d < DIM; d++) s = fmaf(r[d], r[d], s);
        g_ee[k] = s;
    }
}

// ---------------------------------------------------------------------------
// Main: distance GEMM (sequential-d FMA chains, two chains per f32x2 lane)
//       + argmin + quantized write + loss partials
// ---------------------------------------------------------------------------
// smem layout (floats):
//   xs    : float [64][MT]              x tile, d-major           16384 f
//   epair : ull   [256][EP_ULL]         (e_2p[d], e_2p+1[d])      33280 f
//   see   : float [NUM_K]                                           512 f
//   redv  : float [NTY][MT]                                        1024 f
//   redi  : int   [NTY][MT]                                        1024 f
//   sidx  : int   [MT]                                              256 f
#define SM_XS    0
#define SM_EP    (SM_XS + DIM * MT)
#define SM_SEE   (SM_EP + 256 * EP_ULL * 2)
#define SM_REDV  (SM_SEE + NUM_K)
#define SM_REDI  (SM_REDV + NTY * MT)
#define SM_SIDX  (SM_REDI + NTY * MT)
#define SM_TOTF  (SM_SIDX + MT)
#define SMEM_BYTES (SM_TOTF * 4)

__global__ void __launch_bounds__(NTH, 1)
vq_main(const float* __restrict__ inp, const float* __restrict__ emb,
        float* __restrict__ out) {
    extern __shared__ float smem[];
    float* xs   = smem + SM_XS;
    ull*   ep   = (ull*)(smem + SM_EP);
    float* epf  = smem + SM_EP;
    float* see  = smem + SM_SEE;
    float* redv = smem + SM_REDV;
    int*   redi = (int*)(smem + SM_REDI);
    int*   sidx = (int*)(smem + SM_SIDX);

    const int tid = threadIdx.x;
    const int b   = blockIdx.x >> 5;          // 32 t-tiles per batch
    const int t0  = (blockIdx.x & 31) * MT;
    const float* base = inp + (size_t)b * DIM * T_LEN + t0;

    // ---- load x tile: inputs[b, d, t0..t0+255] -> xs[d][m] ----
#pragma unroll
    for (int it = 0; it < (DIM * MT / 4) / NTH; it++) {
        int i = tid + it * NTH;
        int d = i >> 6;                 // 64 float4 per d-row
        int c = i & 63;
        float4 v = *(const float4*)(base + (size_t)d * T_LEN + c * 4);
        *(float4*)(xs + d * MT + c * 4) = v;
    }
    // ---- build emb pair-interleaved tile ----
    // ep[p][d] = (emb[2p][d], emb[2p+1][d]);  16384 ulls, 64 per thread
#pragma unroll
    for (int it = 0; it < (256 * DIM) / NTH; it++) {
        int i = tid + it * NTH;
        int p = i >> 6, d = i & 63;
        float2 v;
        v.x = emb[(2 * p + 0) * DIM + d];
        v.y = emb[(2 * p + 1) * DIM + d];
        *(float2*)(epf + (p * EP_ULL + d) * 2) = v;
    }
    for (int i = tid; i < NUM_K; i += NTH) see[i] = g_ee[i];
    __syncthreads();

    const int tx = tid & 63;
    const int ty = tid >> 6;

    // ---- per-vector |x|^2 (order irrelevant; sequential anyway) ----
    float xx[VT];
#pragma unroll
    for (int j = 0; j < VT; j++) {
        int m = tx + 64 * j;
        float s = 0.f;
#pragma unroll
        for (int d = 0; d < DIM; d++) {
            float v = xs[d * MT + m];
            s = fmaf(v, v, s);
        }
        xx[j] = s;
    }

    float minv[VT];
    int   mini[VT];
#pragma unroll
    for (int j = 0; j < VT; j++) { minv[j] = 3.4e38f; mini[j] = 0; }

    for (int pass = 0; pass < NPASS; pass++) {
        const int pbase = ty * (256 / NTY) + pass * KPP;
        const ull* eprow = ep + pbase * EP_ULL;

        ull acc[VT][KPP];
#pragma unroll
        for (int j = 0; j < VT; j++)
#pragma unroll
            for (int p = 0; p < KPP; p++) acc[j][p] = 0ull;

        // Sequential d-chain: each f32x2 lane is an exact in-order f32 FMA
        // chain (matches Eigen-gebp / cublas-SIMT per-element k order).
#pragma unroll 8
        for (int d = 0; d < DIM; d++) {
            ull xv[VT], ev[KPP];
#pragma unroll
            for (int j = 0; j < VT; j++) xv[j] = dup2(xs[d * MT + tx + 64 * j]);
#pragma unroll
            for (int p = 0; p < KPP; p++) ev[p] = eprow[p * EP_ULL + d];
#pragma unroll
            for (int j = 0; j < VT; j++)
#pragma unroll
                for (int p = 0; p < KPP; p++) fma2(acc[j][p], xv[j], ev[p]);
        }

        // dist = fl(fl(xx - 2*dot) + ee)  — bit-identical to reference expr.
        // ascending code order + strict '<' == first-occurrence argmin.
#pragma unroll
        for (int p = 0; p < KPP; p++) {
            int k0 = 2 * (pbase + p);
            float ee0 = see[k0], ee1 = see[k0 + 1];
#pragma unroll
            for (int j = 0; j < VT; j++) {
                float2 dt = unpack2(acc[j][p]);
                float d0 = fmaf(-2.0f, dt.x, xx[j]) + ee0;
                float d1 = fmaf(-2.0f, dt.y, xx[j]) + ee1;
                if (d0 < minv[j]) { minv[j] = d0; mini[j] = k0; }
                if (d1 < minv[j]) { minv[j] = d1; mini[j] = k0 + 1; }
            }
        }
    }

    // ---- cross-ty argmin reduction (ty ascending == code ascending) ----
#pragma unroll
    for (int j = 0; j < VT; j++) {
        redv[ty * MT + tx + 64 * j] = minv[j];
        redi[ty * MT + tx + 64 * j] = mini[j];
    }
    __syncthreads();
    {
        int m = tid;
        float bv = redv[m];
        int   bi = redi[m];
#pragma unroll
        for (int q = 1; q < NTY; q++) {
            float v = redv[q * MT + m];
            if (v < bv) { bv = v; bi = redi[q * MT + m]; }
        }
        sidx[m] = bi;
        out[IDX_OFF + (size_t)b * T_LEN + t0 + m] = (float)bi;
    }
    __syncthreads();

    // ---- write quantized [b,d,t] + accumulate (q-x)^2 ----
    float* qbase = out + (size_t)b * DIM * T_LEN + t0;
    float lacc = 0.f;
#pragma unroll
    for (int it = 0; it < (DIM * MT / 4) / NTH; it++) {
        int i = tid + it * NTH;
        int d = i >> 6;
        int c = i & 63;
        int m0 = c * 4;
        int i0 = sidx[m0], i1 = sidx[m0 + 1], i2 = sidx[m0 + 2], i3 = sidx[m0 + 3];
        float4 q;
        q.x = epf[(i0 >> 1) * (EP_ULL * 2) + d * 2 + (i0 & 1)];
        q.y = epf[(i1 >> 1) * (EP_ULL * 2) + d * 2 + (i1 & 1)];
        q.z = epf[(i2 >> 1) * (EP_ULL * 2) + d * 2 + (i2 & 1)];
        q.w = epf[(i3 >> 1) * (EP_ULL * 2) + d * 2 + (i3 & 1)];
        *(float4*)(qbase + (size_t)d * T_LEN + m0) = q;

        const float* xrow = xs + d * MT;
        float dx;
        dx = q.x - xrow[m0 + 0]; lacc = fmaf(dx, dx, lacc);
        dx = q.y - xrow[m0 + 1]; lacc = fmaf(dx, dx, lacc);
        dx = q.z - xrow[m0 + 2]; lacc = fmaf(dx, dx, lacc);
        dx = q.w - xrow[m0 + 3]; lacc = fmaf(dx, dx, lacc);
    }

    // deterministic block reduction: warp shuffle -> smem -> thread 0
#pragma unroll
    for (int off = 16; off; off >>= 1)
        lacc += __shfl_xor_sync(0xffffffffu, lacc, off);
    __syncthreads();                 // done with redv, reuse it
    if ((tid & 31) == 0) redv[tid >> 5] = lacc;
    __syncthreads();
    if (tid == 0) {
        double s = 0.0;
#pragma unroll
        for (int w = 0; w < NTH / 32; w++) s += (double)redv[w];
        g_partial[blockIdx.x] = s;
    }
}

// ---------------------------------------------------------------------------
// Finalize: deterministic sum of block partials -> loss scalar
// ---------------------------------------------------------------------------
__global__ void vq_loss(float* __restrict__ out) {
    int lane = threadIdx.x;           // 32 threads
    double s = 0.0;
    for (int i = 0; i < NBLOCKS / 32; i++)
        s += g_partial[lane * (NBLOCKS / 32) + i];
#pragma unroll
    for (int off = 16; off; off >>= 1)
        s += __shfl_xor_sync(0xffffffffu, s, off);
    if (lane == 0)
        out[LOSS_OFF] = (float)(s * (1.25 / (double)((size_t)B_LEN * DIM * T_LEN)));
}

// ---------------------------------------------------------------------------
extern "C" void kernel_launch(void* const* d_in, const int* in_sizes, int n_in,
                              void* d_out, int out_size) {
    const float* inp = (const float*)d_in[0];   // [32, 64, 8192] f32
    const float* emb = (const float*)d_in[1];   // [512, 64] f32
    float* out = (float*)d_out;

    cudaFuncSetAttribute(vq_main, cudaFuncAttributeMaxDynamicSharedMemorySize,
                         SMEM_BYTES);

    vq_prep<<<1, NUM_K>>>(emb);
    vq_main<<<NBLOCKS, NTH, SMEM_BYTES>>>(inp, emb, out);
    vq_loss<<<1, 32>>>(out);
}